// round 6
// baseline (speedup 1.0000x reference)
#include <cuda_runtime.h>
#include <math.h>

// Problem constants (shapes fixed by setup_inputs)
#define C_DIM   20
#define C2      10          // channel pairs
#define HW      524288      // 512*1024
#define HW2     262144      // HW/2 (float2 units)
#define HW2_SH  18          // log2(HW2)
#define BLK     256
#define TILES_PER_THREAD 4

// Prep output: normalized prototypes [m][c] + per-row squared norms
__device__ float g_proto[C_DIM * C_DIM];
__device__ float g_psqn[C_DIM];

__device__ __forceinline__ float sqrt_approx(float v) {
    float r; asm("sqrt.approx.f32 %0, %1;" : "=f"(r) : "f"(v)); return r;
}
__device__ __forceinline__ float rsqrt_approx(float v) {
    float r; asm("rsqrt.approx.f32 %0, %1;" : "=f"(r) : "f"(v)); return r;
}
// packed fp32x2 FMA: d = a*b + d   (FFMA2 — only reachable via PTX)
__device__ __forceinline__ void ffma2(unsigned long long& d,
                                      unsigned long long a,
                                      unsigned long long b) {
    asm("fma.rn.f32x2 %0, %1, %2, %0;" : "+l"(d) : "l"(a), "l"(b));
}
__device__ __forceinline__ unsigned long long pack2(float lo, float hi) {
    unsigned long long r;
    asm("mov.b64 %0, {%1, %2};" : "=l"(r) : "f"(lo), "f"(hi));
    return r;
}
__device__ __forceinline__ void unpack2(float& lo, float& hi, unsigned long long v) {
    asm("mov.b64 {%0, %1}, %2;" : "=f"(lo), "=f"(hi) : "l"(v));
}

// ---------------------------------------------------------------------------
// Prep: normalize prototype rows (dim=1), store rows + squared norms.
// ---------------------------------------------------------------------------
__global__ void proto_prep_kernel(const float* __restrict__ protos) {
    int m = threadIdx.x;
    if (m < C_DIM) {
        float v[C_DIM];
        float sq = 0.f;
        #pragma unroll
        for (int c = 0; c < C_DIM; c++) {
            v[c] = protos[m * C_DIM + c];
            sq = fmaf(v[c], v[c], sq);
        }
        float inv = 1.0f / fmaxf(sqrtf(sq), 1e-12f);
        float s = 0.f;
        #pragma unroll
        for (int c = 0; c < C_DIM; c++) {
            float pv = v[c] * inv;
            g_proto[m * C_DIM + c] = pv;
            s = fmaf(pv, pv, s);
        }
        g_psqn[m] = s;
    }
}

// ---------------------------------------------------------------------------
// Main kernel: 2 consecutive pixels per thread-tile (one float2 along W),
// grid-stride over TILES_PER_THREAD tiles with software pipelining:
// while tile i's m-loop runs, tile i+1's 20 LDG.64 are already in flight.
// Channel-pair FFMA2 dot products against smem prototype rows (LDS.128).
//   input  float2 idx: b*C*HW2 + c*HW2 + rem
//   output float2 idx: b*C*HW2 + m*HW2 + rem
// ---------------------------------------------------------------------------
__global__ __launch_bounds__(BLK, 2)
void isomax_dist_kernel(const float* __restrict__ in,
                        const float* __restrict__ scale_p,
                        float* __restrict__ out,
                        int n_tiles) {
    __shared__ float sp[C_DIM * C_DIM];   // 80B rows = 5 x 16B, 16B-aligned
    __shared__ float spsn[C_DIM];
    for (int i = threadIdx.x; i < C_DIM * C_DIM; i += BLK)
        sp[i] = g_proto[i];
    if (threadIdx.x < C_DIM)
        spsn[threadIdx.x] = g_psqn[threadIdx.x];
    __syncthreads();

    const float sneg = -fabsf(__ldg(scale_p));   // logits = -|scale| * dist

    const float2* __restrict__ in2  = (const float2*)in;
    float2*       __restrict__ out2 = (float2*)out;

    const unsigned stride = gridDim.x * BLK;
    unsigned q = blockIdx.x * BLK + threadIdx.x;
    if (q >= (unsigned)n_tiles) return;

    unsigned b    = q >> HW2_SH;
    unsigned rem  = q & (HW2 - 1u);
    unsigned base2 = b * (C_DIM * HW2) + rem;

    // Prologue: load first tile's channels (20 x LDG.64, coalesced).
    float2 raw[C_DIM];
    #pragma unroll
    for (int c = 0; c < C_DIM; c++)
        raw[c] = in2[base2 + (unsigned)c * HW2];

    while (true) {
        // Pack along channel pairs per pixel; fold in norm accumulation.
        unsigned long long xpA[C2], xpB[C2];
        unsigned long long sqA = 0ull, sqB = 0ull;
        #pragma unroll
        for (int c2 = 0; c2 < C2; c2++) {
            float2 va = raw[2 * c2];
            float2 vb = raw[2 * c2 + 1];
            unsigned long long pa = pack2(va.x, vb.x);   // pixel A
            unsigned long long pb = pack2(va.y, vb.y);   // pixel B
            xpA[c2] = pa; ffma2(sqA, pa, pa);
            xpB[c2] = pb; ffma2(sqB, pb, pb);
        }

        // Prefetch: issue next tile's 20 loads NOW; they fly during the m-loop.
        unsigned qn = q + stride;
        bool more = qn < (unsigned)n_tiles;
        unsigned bn    = qn >> HW2_SH;
        unsigned remn  = qn & (HW2 - 1u);
        unsigned basen = bn * (C_DIM * HW2) + remn;
        if (more) {
            #pragma unroll
            for (int c = 0; c < C_DIM; c++)
                raw[c] = in2[basen + (unsigned)c * HW2];
        }

        float loA, hiA, loB, hiB;
        unpack2(loA, hiA, sqA);
        unpack2(loB, hiB, sqB);
        float xsqA = loA + hiA, xsqB = loB + hiB;
        float invA = rsqrt_approx(fmaxf(xsqA, 1e-24f));
        float invB = rsqrt_approx(fmaxf(xsqB, 1e-24f));
        float xnA = xsqA * invA * invA;     // ||x_hat||^2
        float xnB = xsqB * invB * invB;
        float n2iA = -2.f * invA;
        float n2iB = -2.f * invB;

        #pragma unroll 1
        for (int m = 0; m < C_DIM; m++) {
            const ulonglong2* pr = (const ulonglong2*)&sp[m * C_DIM]; // 5 LDS.128
            unsigned long long accA = 0ull, accB = 0ull;
            #pragma unroll
            for (int c4 = 0; c4 < C2 / 2; c4++) {
                ulonglong2 pp = pr[c4];
                ffma2(accA, xpA[2 * c4],     pp.x);
                ffma2(accA, xpA[2 * c4 + 1], pp.y);
                ffma2(accB, xpB[2 * c4],     pp.x);
                ffma2(accB, xpB[2 * c4 + 1], pp.y);
            }
            float psn = spsn[m];

            float a0, a1, b0, b1;
            unpack2(a0, a1, accA);
            unpack2(b0, b1, accB);
            float dotA = a0 + a1;
            float dotB = b0 + b1;
            float d2A = fmaf(dotA, n2iA, xnA + psn);
            float d2B = fmaf(dotB, n2iB, xnB + psn);
            d2A = fmaxf(d2A, 0.f);
            d2B = fmaxf(d2B, 0.f);

            float2 o;
            o.x = sneg * sqrt_approx(d2A);
            o.y = sneg * sqrt_approx(d2B);
            out2[base2 + (unsigned)m * HW2] = o;
        }

        if (!more) break;
        q = qn;
        base2 = basen;
    }
}

extern "C" void kernel_launch(void* const* d_in, const int* in_sizes, int n_in,
                              void* d_out, int out_size) {
    const float* features = (const float*)d_in[0];  // [8,20,512,1024] f32
    const float* protos   = (const float*)d_in[1];  // [20,20] f32
    const float* dscale   = (const float*)d_in[2];  // [1] f32

    proto_prep_kernel<<<1, 32>>>(protos);

    int n_tiles = (in_sizes[0] / C_DIM) / 2;        // pixel pairs (float2 tiles)
    int grid = (n_tiles + BLK * TILES_PER_THREAD - 1) / (BLK * TILES_PER_THREAD);
    isomax_dist_kernel<<<grid, BLK>>>(features, dscale, (float*)d_out, n_tiles);
}

// round 7
// speedup vs baseline: 1.1435x; 1.1435x over previous
#include <cuda_runtime.h>
#include <math.h>

// Problem constants (shapes fixed by setup_inputs)
#define C_DIM   20
#define C2      10          // channel pairs
#define HW      524288      // 512*1024
#define HW4     131072      // HW/4 (float4 units)
#define HW4_SH  17          // log2(HW4)
#define BLK     256

// Prep output: normalized prototypes [m][c] + per-row squared norms
__device__ float g_proto[C_DIM * C_DIM];
__device__ float g_psqn[C_DIM];

__device__ __forceinline__ float sqrt_approx(float v) {
    float r; asm("sqrt.approx.f32 %0, %1;" : "=f"(r) : "f"(v)); return r;
}
__device__ __forceinline__ float rsqrt_approx(float v) {
    float r; asm("rsqrt.approx.f32 %0, %1;" : "=f"(r) : "f"(v)); return r;
}
// packed fp32x2 FMA: d = a*b + d   (FFMA2 — only reachable via PTX)
__device__ __forceinline__ void ffma2(unsigned long long& d,
                                      unsigned long long a,
                                      unsigned long long b) {
    asm("fma.rn.f32x2 %0, %1, %2, %0;" : "+l"(d) : "l"(a), "l"(b));
}
__device__ __forceinline__ unsigned long long pack2(float lo, float hi) {
    unsigned long long r;
    asm("mov.b64 %0, {%1, %2};" : "=l"(r) : "f"(lo), "f"(hi));
    return r;
}
__device__ __forceinline__ void unpack2(float& lo, float& hi, unsigned long long v) {
    asm("mov.b64 {%0, %1}, %2;" : "=f"(lo), "=f"(hi) : "l"(v));
}

// ---------------------------------------------------------------------------
// Prep: normalize prototype rows (dim=1), store rows + squared norms.
// ---------------------------------------------------------------------------
__global__ void proto_prep_kernel(const float* __restrict__ protos) {
    int m = threadIdx.x;
    if (m < C_DIM) {
        float v[C_DIM];
        float sq = 0.f;
        #pragma unroll
        for (int c = 0; c < C_DIM; c++) {
            v[c] = protos[m * C_DIM + c];
            sq = fmaf(v[c], v[c], sq);
        }
        float inv = 1.0f / fmaxf(sqrtf(sq), 1e-12f);
        float s = 0.f;
        #pragma unroll
        for (int c = 0; c < C_DIM; c++) {
            float pv = v[c] * inv;
            g_proto[m * C_DIM + c] = pv;
            s = fmaf(pv, pv, s);
        }
        g_psqn[m] = s;
    }
}

// ---------------------------------------------------------------------------
// Main kernel (R3 structure): 4 consecutive pixels per thread (one float4
// along W). Channel-pair packing + fma.rn.f32x2 dot products against smem
// prototype rows (LDS.128). All global traffic uses streaming cache policy
// (__ldcs / __stcs): zero reuse, evict-first, keep L2 clean.
//   input  float4 idx: b*C*HW4 + c*HW4 + rem
//   output float4 idx: b*C*HW4 + m*HW4 + rem
// ---------------------------------------------------------------------------
__global__ __launch_bounds__(BLK, 2)
void isomax_dist_kernel(const float* __restrict__ in,
                        const float* __restrict__ scale_p,
                        float* __restrict__ out) {
    __shared__ float sp[C_DIM * C_DIM];   // 80B rows = 5 x 16B, 16B-aligned
    __shared__ float spsn[C_DIM];
    for (int i = threadIdx.x; i < C_DIM * C_DIM; i += BLK)
        sp[i] = g_proto[i];
    if (threadIdx.x < C_DIM)
        spsn[threadIdx.x] = g_psqn[threadIdx.x];
    __syncthreads();

    const float sneg = -fabsf(__ldg(scale_p));   // logits = -|scale| * dist

    const float4* __restrict__ in4  = (const float4*)in;
    float4*       __restrict__ out4 = (float4*)out;

    unsigned q   = blockIdx.x * BLK + threadIdx.x;   // global float4-pixel index
    unsigned b   = q >> HW4_SH;
    unsigned rem = q & (HW4 - 1u);
    unsigned base4 = b * (C_DIM * HW4) + rem;

    // Load 20 channels for 4 pixels (20 x LDG.128.CS, coalesced, deep MLP);
    // pack along channel pairs and fold in the squared-norm accumulation.
    unsigned long long xp[C2 * 4];
    unsigned long long xsq2[4] = {0ull, 0ull, 0ull, 0ull};
    #pragma unroll
    for (int c2 = 0; c2 < C2; c2++) {
        float4 a  = __ldcs(&in4[base4 + (unsigned)(2 * c2)     * HW4]);
        float4 b4 = __ldcs(&in4[base4 + (unsigned)(2 * c2 + 1) * HW4]);
        unsigned long long p0 = pack2(a.x, b4.x);
        unsigned long long p1 = pack2(a.y, b4.y);
        unsigned long long p2 = pack2(a.z, b4.z);
        unsigned long long p3 = pack2(a.w, b4.w);
        xp[c2 * 4 + 0] = p0; ffma2(xsq2[0], p0, p0);
        xp[c2 * 4 + 1] = p1; ffma2(xsq2[1], p1, p1);
        xp[c2 * 4 + 2] = p2; ffma2(xsq2[2], p2, p2);
        xp[c2 * 4 + 3] = p3; ffma2(xsq2[3], p3, p3);
    }

    // Per-pixel: inv = 1/||x|| (rsqrt, clamped), xn = ||x_hat||^2, n2i = -2*inv
    float xn[4], n2i[4];
    #pragma unroll
    for (int j = 0; j < 4; j++) {
        float lo, hi;
        unpack2(lo, hi, xsq2[j]);
        float xsq = lo + hi;
        float inv = rsqrt_approx(fmaxf(xsq, 1e-24f));
        xn[j]  = xsq * inv * inv;
        n2i[j] = -2.f * inv;
    }

    #pragma unroll 1
    for (int m = 0; m < C_DIM; m++) {
        // prototype row m as 5 x ulonglong2 (each = 2 channel pairs), LDS.128
        const ulonglong2* pr = (const ulonglong2*)&sp[m * C_DIM];
        unsigned long long acc[4] = {0ull, 0ull, 0ull, 0ull};
        #pragma unroll
        for (int c4 = 0; c4 < C2 / 2; c4++) {
            ulonglong2 pp = pr[c4];
            ffma2(acc[0], xp[(2 * c4) * 4 + 0], pp.x);
            ffma2(acc[1], xp[(2 * c4) * 4 + 1], pp.x);
            ffma2(acc[2], xp[(2 * c4) * 4 + 2], pp.x);
            ffma2(acc[3], xp[(2 * c4) * 4 + 3], pp.x);
            ffma2(acc[0], xp[(2 * c4 + 1) * 4 + 0], pp.y);
            ffma2(acc[1], xp[(2 * c4 + 1) * 4 + 1], pp.y);
            ffma2(acc[2], xp[(2 * c4 + 1) * 4 + 2], pp.y);
            ffma2(acc[3], xp[(2 * c4 + 1) * 4 + 3], pp.y);
        }
        float psn = spsn[m];

        float4 o;
        #pragma unroll
        for (int j = 0; j < 4; j++) {
            float lo, hi;
            unpack2(lo, hi, acc[j]);
            float dot = lo + hi;
            float d2 = fmaf(dot, n2i[j], xn[j] + psn);
            d2 = fmaxf(d2, 0.f);
            ((float*)&o)[j] = sneg * sqrt_approx(d2);
        }
        __stcs(&out4[base4 + (unsigned)m * HW4], o);   // STG.128.CS streaming
    }
}

extern "C" void kernel_launch(void* const* d_in, const int* in_sizes, int n_in,
                              void* d_out, int out_size) {
    const float* features = (const float*)d_in[0];  // [8,20,512,1024] f32
    const float* protos   = (const float*)d_in[1];  // [20,20] f32
    const float* dscale   = (const float*)d_in[2];  // [1] f32

    proto_prep_kernel<<<1, 32>>>(protos);

    int n_pix4 = (in_sizes[0] / C_DIM) / 4;         // float4 pixel groups
    int grid = (n_pix4 + BLK - 1) / BLK;
    isomax_dist_kernel<<<grid, BLK>>>(features, dscale, (float*)d_out);
}